// round 12
// baseline (speedup 1.0000x reference)
#include <cuda_runtime.h>
#include <cstdint>

// LFR: M=7, N=6, LEFT=3, D=80 floats = 320B/frame = 10 v8(32B) per frame,
// 70 v8 per output row (7 frames).
#define MM 7
#define NN 6
#define LEFTP 3
#define DD 80
#define V8F 10     /* 32B units per frame */
#define V8R 70     /* 32B units per output row */
#define RPB 16     /* rows per block -> 1120 v8 per block */
#define TPB 224    /* 7 warps; 1120/224 = 5 elements per thread */
#define EPT 5

__device__ __forceinline__ int t_all_of(int L) {
    int c6    = (L + 5) / 6;          // ceil(L/6)
    int delta = L + 9 - 6 * c6;       // prepad - N*(n_lfr-1)
    int rp    = 7 - delta; if (rp < 0) rp = 0;
    return 3 + L + rp;
}

// 256-bit load, L2 evict_last: x (84MB < 126MB L2) is re-read identically every
// graph replay; keep it resident (R8: -1.5us). v8.b32 is the width ptxas allows
// the bare evict_last qualifier on.
__device__ __forceinline__ void ldg256_el(const uint32_t* p, uint32_t* v) {
    asm volatile("ld.global.nc.L2::evict_last.v8.b32 {%0,%1,%2,%3,%4,%5,%6,%7}, [%8];"
                 : "=r"(v[0]), "=r"(v[1]), "=r"(v[2]), "=r"(v[3]),
                   "=r"(v[4]), "=r"(v[5]), "=r"(v[6]), "=r"(v[7])
                 : "l"(p));
}
// 256-bit streaming store (evict-first: don't let the write stream evict x).
__device__ __forceinline__ void stg256_cs(uint32_t* p, const uint32_t* v) {
    asm volatile("st.global.cs.v8.b32 [%0], {%1,%2,%3,%4,%5,%6,%7,%8};"
                 :: "l"(p),
                    "r"(v[0]), "r"(v[1]), "r"(v[2]), "r"(v[3]),
                    "r"(v[4]), "r"(v[5]), "r"(v[6]), "r"(v[7])
                 : "memory");
}

// grid = (ceil(nf/RPB), B), block = TPB. Units below are 32B (v8) elements.
// Block covers e in [0,1120) of rows [f0, f0+16); thread owns e = tid + s*224.
// Decode: f_loc = e/70, r = e%70.  out[b,f,r] = x8[b, src_v8]:
//   interior row:  src_v8 = (6f-3)*10 + r            (contiguous slice)
//   boundary row:  m = r/10; t = 6f+m; src = t<L+3 ? max(t-3,0) : fb
__global__ __launch_bounds__(TPB)
void lfr_fused_kernel(const uint32_t* __restrict__ x8,
                      uint32_t* __restrict__ out8,
                      const int* __restrict__ lens,
                      float* __restrict__ newlen,
                      int T, int nf, int B, int write_newlen) {
    const int b   = blockIdx.y;
    const int f0  = blockIdx.x * RPB;
    const int tid = threadIdx.x;

    const int L     = __ldg(&lens[b]);
    const int limit = L + LEFTP;

    // Per-batch new_len written once, by block (0, b).
    if (write_newlen && blockIdx.x == 0 && tid == 0)
        newlen[b] = (float)(t_all_of(L) / NN);

    // Does this block contain any row touching t >= limit (needs fb)?
    const int fLast    = min(f0 + RPB - 1, nf - 1);
    const bool need_fb = (NN * fLast + NN) >= limit;   // block-uniform

    __shared__ int s_max[TPB / 32];
    int fb = 0;
    if (need_fb) {
        // Tmax = max over batch of T_all (lens[] is tiny and L2-hot).
        int v = 0;
        if (tid < B) v = t_all_of(__ldg(&lens[tid]));
        #pragma unroll
        for (int off = 16; off; off >>= 1)
            v = max(v, __shfl_xor_sync(0xffffffffu, v, off));
        if ((tid & 31) == 0) s_max[tid >> 5] = v;
        __syncthreads();
        int Tmax = s_max[0];
        #pragma unroll
        for (int w = 1; w < TPB / 32; w++) Tmax = max(Tmax, s_max[w]);
        const int jmax = Tmax - 1;                     // padded index for masked slots
        fb = (jmax < LEFTP + T) ? (jmax - LEFTP) : (L - 1);
    }

    // Pointers in 32B units (8 x u32 per element).
    const size_t xb = (size_t)b * T * V8F;                 // x base (v8 units)
    const size_t ob = ((size_t)b * nf + f0) * V8R;         // out base (v8 units, row f0)

    uint32_t v[EPT][8];
    bool     ok[EPT];
    size_t   oo[EPT];

    #pragma unroll
    for (int s = 0; s < EPT; s++) {
        const int e     = tid + s * TPB;                   // 0..1119
        const int f_loc = (e * 937) >> 16;                 // exact e/70 for e<1120
        const int r     = e - f_loc * V8R;                 // e%70
        const int f     = f0 + f_loc;
        ok[s] = (f < nf);
        oo[s] = ob + e;
        if (!ok[s]) continue;
        int src_v8;
        if (f >= 1 && (NN * f + NN) < limit) {
            // Interior row: contiguous slice of x.
            src_v8 = (NN * f - LEFTP) * V8F + r;
        } else {
            // Boundary row: per-element clamp / fallback.
            const int m   = (r * 205) >> 11;               // exact r/10 for r<70
            const int t   = NN * f + m;
            const int tm3 = t - LEFTP;
            const int src = (t < limit) ? (tm3 < 0 ? 0 : tm3) : fb;
            src_v8 = src * V8F + (r - m * V8F);
        }
        ldg256_el(x8 + (xb + src_v8) * 8, v[s]);
    }

    #pragma unroll
    for (int s = 0; s < EPT; s++)
        if (ok[s]) stg256_cs(out8 + oo[s] * 8, v[s]);
}

extern "C" void kernel_launch(void* const* d_in, const int* in_sizes, int n_in,
                              void* d_out, int out_size) {
    const float* x    = (const float*)d_in[0];
    const int*   lens = (const int*)d_in[1];

    int B = in_sizes[1];                 // 64
    int T = in_sizes[0] / (B * DD);      // 4096

    long long per = (long long)B * (MM * DD);   // output elems per frame-row across batch
    long long nf;
    int write_newlen = 0;
    if (out_size > B && ((long long)(out_size - B) % per) == 0) {
        write_newlen = 1;
        nf = ((long long)out_size - B) / per;
    } else {
        nf = (long long)out_size / per;
    }

    float* out    = (float*)d_out;
    float* newlen = out + (long long)B * nf * (MM * DD);

    dim3 grid(((int)nf + RPB - 1) / RPB, B);
    lfr_fused_kernel<<<grid, TPB>>>((const uint32_t*)x, (uint32_t*)out,
                                    lens, newlen, T, (int)nf, B, write_newlen);
}